// round 4
// baseline (speedup 1.0000x reference)
#include <cuda_runtime.h>
#include <math.h>

#define BATCH   2
#define SEQ     2048
#define DMODEL  1024
#define NHEADS  16
#define HD      64

// ---------------- scratch (no allocations allowed) ----------------
__device__ float g_Q[BATCH * NHEADS * SEQ * HD];     // 16 MB
__device__ float g_K[BATCH * NHEADS * SEQ * HD];     // 16 MB
__device__ float g_V[BATCH * NHEADS * SEQ * HD];     // 16 MB
__device__ float g_att[BATCH * SEQ * DMODEL];        // 16 MB
__device__ float g_cos[SEQ * 32];
__device__ float g_sin[SEQ * 32];

// ---------------- RoPE table (fp64 for large-angle accuracy) ----------------
__global__ void rope_table_kernel() {
    int idx = blockIdx.x * blockDim.x + threadIdx.x;
    if (idx >= SEQ * 32) return;
    int s = idx / 32, i = idx % 32;
    double inv = exp(-((double)(2 * i) / 64.0) * log(10000.0));
    double ang = (double)s * inv;
    double sn, cs;
    sincos(ang, &sn, &cs);
    g_cos[idx] = (float)cs;
    g_sin[idx] = (float)sn;
}

// ---------------- QKV GEMM (double-buffered): x[4096,1024] @ W[1024,3072] + b ----------------
__global__ __launch_bounds__(256) void qkv_gemm_kernel(
    const float* __restrict__ A, const float* __restrict__ B,
    const float* __restrict__ bias) {
    const int K = DMODEL;          // 1024
    const int N = 3 * DMODEL;      // 3072
    __shared__ float As[2][16][132];
    __shared__ float Bs[2][16][132];

    int tid = threadIdx.x;
    int m0 = blockIdx.y * 128;
    int n0 = blockIdx.x * 128;
    int trow = tid / 16;           // 0..15
    int tcol = tid % 16;           // 0..15

    // per-thread load coordinates, t = 0,1
    int arow[2], akc[2], brow[2], bnc[2];
#pragma unroll
    for (int t = 0; t < 2; t++) {
        int idx = tid + 256 * t;
        arow[t] = idx >> 2;  akc[t] = idx & 3;
        brow[t] = idx >> 5;  bnc[t] = idx & 31;
    }

    float acc[8][8];
#pragma unroll
    for (int i = 0; i < 8; i++)
#pragma unroll
        for (int j = 0; j < 8; j++) acc[i][j] = 0.f;

    float4 pa[2], pb[2];
    // preload k-tile 0
#pragma unroll
    for (int t = 0; t < 2; t++) {
        pa[t] = *(const float4*)&A[(size_t)(m0 + arow[t]) * K + 4 * akc[t]];
        pb[t] = *(const float4*)&B[(size_t)brow[t] * N + n0 + 4 * bnc[t]];
    }
#pragma unroll
    for (int t = 0; t < 2; t++) {
        As[0][4 * akc[t] + 0][arow[t]] = pa[t].x;
        As[0][4 * akc[t] + 1][arow[t]] = pa[t].y;
        As[0][4 * akc[t] + 2][arow[t]] = pa[t].z;
        As[0][4 * akc[t] + 3][arow[t]] = pa[t].w;
        *(float4*)&Bs[0][brow[t]][4 * bnc[t]] = pb[t];
    }
    __syncthreads();

    int buf = 0;
    for (int k0 = 0; k0 < K; k0 += 16) {
        int kn = k0 + 16;
        bool has_next = kn < K;
        if (has_next) {
#pragma unroll
            for (int t = 0; t < 2; t++) {
                pa[t] = *(const float4*)&A[(size_t)(m0 + arow[t]) * K + kn + 4 * akc[t]];
                pb[t] = *(const float4*)&B[(size_t)(kn + brow[t]) * N + n0 + 4 * bnc[t]];
            }
        }
#pragma unroll
        for (int kk = 0; kk < 16; kk++) {
            float a[8], b[8];
            *(float4*)&a[0] = *(const float4*)&As[buf][kk][trow * 8];
            *(float4*)&a[4] = *(const float4*)&As[buf][kk][trow * 8 + 4];
            *(float4*)&b[0] = *(const float4*)&Bs[buf][kk][tcol * 8];
            *(float4*)&b[4] = *(const float4*)&Bs[buf][kk][tcol * 8 + 4];
#pragma unroll
            for (int i = 0; i < 8; i++)
#pragma unroll
                for (int j = 0; j < 8; j++) acc[i][j] += a[i] * b[j];
        }
        if (has_next) {
            int nb = buf ^ 1;
#pragma unroll
            for (int t = 0; t < 2; t++) {
                As[nb][4 * akc[t] + 0][arow[t]] = pa[t].x;
                As[nb][4 * akc[t] + 1][arow[t]] = pa[t].y;
                As[nb][4 * akc[t] + 2][arow[t]] = pa[t].z;
                As[nb][4 * akc[t] + 3][arow[t]] = pa[t].w;
                *(float4*)&Bs[nb][brow[t]][4 * bnc[t]] = pb[t];
            }
            __syncthreads();
            buf = nb;
        }
    }

    // epilogue: bias + scatter into [B,H,S,hd] layout
#pragma unroll
    for (int i = 0; i < 8; i++) {
        int m = m0 + trow * 8 + i;
        int bb = m / SEQ, s = m % SEQ;
#pragma unroll
        for (int j = 0; j < 8; j += 4) {
            int n = n0 + tcol * 8 + j;
            float4 v;
            v.x = acc[i][j + 0] + bias[n + 0];
            v.y = acc[i][j + 1] + bias[n + 1];
            v.z = acc[i][j + 2] + bias[n + 2];
            v.w = acc[i][j + 3] + bias[n + 3];
            int which = n / DMODEL;            // 0=Q 1=K 2=V
            int nn = n % DMODEL;
            int h = nn / HD, d = nn % HD;      // 4-aligned, same head within float4
            float* dst = (which == 0) ? g_Q : (which == 1) ? g_K : g_V;
            *(float4*)&dst[(size_t)((bb * NHEADS + h) * SEQ + s) * HD + d] = v;
        }
    }
}

// ---------------- RoPE apply (in-place on Q and K) ----------------
__global__ void rope_apply_kernel() {
    int idx = blockIdx.x * blockDim.x + threadIdx.x;
    const int total = BATCH * NHEADS * SEQ * 32;
    if (idx >= total) return;
    int d = idx & 31;
    int s = (idx >> 5) & (SEQ - 1);
    int bh = idx / (32 * SEQ);
    float c = g_cos[s * 32 + d];
    float sn = g_sin[s * 32 + d];
    size_t base = (size_t)(bh * SEQ + s) * HD;
    float q0 = g_Q[base + d], q1 = g_Q[base + d + 32];
    g_Q[base + d]      = q0 * c - q1 * sn;
    g_Q[base + d + 32] = q1 * c + q0 * sn;
    float k0 = g_K[base + d], k1 = g_K[base + d + 32];
    g_K[base + d]      = k0 * c - k1 * sn;
    g_K[base + d + 32] = k1 * c + k0 * sn;
}

// ---------------- Flash attention, fp32, causal ----------------
// grid (S/64, B*H), 256 threads. Thread (r=tid/4, quad=tid%4) owns Q row r fully
// in registers, keys j = jj*4+quad of each 64-key tile, and all 64 output dims
// (partial over its key subset); quad butterfly-reduce at the end.
__global__ __launch_bounds__(256) void attn_kernel() {
    __shared__ float Ks[64][68];
    __shared__ float Vs[64][68];
    int tid = threadIdx.x;
    int qt = blockIdx.x;           // q tile 0..31
    int bh = blockIdx.y;           // 0..31
    int r = tid >> 2;              // 0..63
    int qd = tid & 3;              // quad lane
    const float scale = 0.125f;    // 1/sqrt(64)

    const float* Qbase = &g_Q[(size_t)(bh * SEQ + qt * 64) * HD];
    const float* Kbase = &g_K[(size_t)bh * SEQ * HD];
    const float* Vbase = &g_V[(size_t)bh * SEQ * HD];

    // stage Q tile through Ks, pull own row into registers
#pragma unroll
    for (int t = 0; t < 4; t++) {
        int idx = tid + 256 * t;           // 0..1023
        int j = idx >> 4, dc = idx & 15;
        *(float4*)&Ks[j][dc * 4] = *(const float4*)&Qbase[j * HD + dc * 4];
    }
    __syncthreads();
    float Qreg[64];
#pragma unroll
    for (int dc = 0; dc < 16; dc++)
        *(float4*)&Qreg[dc * 4] = *(const float4*)&Ks[r][dc * 4];
    __syncthreads();

    float acc[64];
#pragma unroll
    for (int d = 0; d < 64; d++) acc[d] = 0.f;
    float m = -1e30f, l = 0.f;

    for (int kt = 0; kt <= qt; kt++) {
#pragma unroll
        for (int t = 0; t < 4; t++) {
            int idx = tid + 256 * t;
            int j = idx >> 4, dc = idx & 15;
            *(float4*)&Ks[j][dc * 4] =
                *(const float4*)&Kbase[(size_t)(kt * 64 + j) * HD + dc * 4];
            *(float4*)&Vs[j][dc * 4] =
                *(const float4*)&Vbase[(size_t)(kt * 64 + j) * HD + dc * 4];
        }
        __syncthreads();

        float p[16];
#pragma unroll
        for (int jj = 0; jj < 16; jj++) {
            int j = jj * 4 + qd;
            float s0 = 0.f, s1 = 0.f, s2 = 0.f, s3 = 0.f;
#pragma unroll
            for (int dc = 0; dc < 16; dc++) {
                float4 kv = *(const float4*)&Ks[j][dc * 4];
                s0 += Qreg[dc * 4 + 0] * kv.x;
                s1 += Qreg[dc * 4 + 1] * kv.y;
                s2 += Qreg[dc * 4 + 2] * kv.z;
                s3 += Qreg[dc * 4 + 3] * kv.w;
            }
            float s = ((s0 + s1) + (s2 + s3)) * scale;
            if (kt == qt && (kt * 64 + j) > (qt * 64 + r)) s = -1e30f;
            p[jj] = s;
        }

        float mloc = p[0];
#pragma unroll
        for (int jj = 1; jj < 16; jj++) mloc = fmaxf(mloc, p[jj]);
        mloc = fmaxf(mloc, __shfl_xor_sync(0xffffffffu, mloc, 1));
        mloc = fmaxf(mloc, __shfl_xor_sync(0xffffffffu, mloc, 2));
        float mnew = fmaxf(m, mloc);
        float corr = __expf(m - mnew);
        l *= corr;
#pragma unroll
        for (int d = 0; d < 64; d++) acc[d] *= corr;
#pragma unroll
        for (int jj = 0; jj < 16; jj++) {
            float e = __expf(p[jj] - mnew);
            p[jj] = e;
            l += e;
        }
        m = mnew;

#pragma unroll
        for (int jj = 0; jj < 16; jj++) {
            int j = jj * 4 + qd;
            float e = p[jj];
#pragma unroll
            for (int dc = 0; dc < 16; dc++) {
                float4 vv = *(const float4*)&Vs[j][dc * 4];
                acc[dc * 4 + 0] += e * vv.x;
                acc[dc * 4 + 1] += e * vv.y;
                acc[dc * 4 + 2] += e * vv.z;
                acc[dc * 4 + 3] += e * vv.w;
            }
        }
        __syncthreads();
    }

    // quad reduce l and acc
    l += __shfl_xor_sync(0xffffffffu, l, 1);
    l += __shfl_xor_sync(0xffffffffu, l, 2);
    float inv_l = 1.f / l;
#pragma unroll
    for (int d = 0; d < 64; d++) {
        float v = acc[d];
        v += __shfl_xor_sync(0xffffffffu, v, 1);
        v += __shfl_xor_sync(0xffffffffu, v, 2);
        acc[d] = v * inv_l;
    }

    int bb = bh >> 4, h = bh & 15;
    int s = qt * 64 + r;
    float* out = &g_att[(size_t)(bb * SEQ + s) * DMODEL + h * HD];
#pragma unroll
    for (int i = 0; i < 4; i++) {
        int d = qd * 16 + i * 4;
        *(float4*)&out[d] = make_float4(acc[d], acc[d + 1], acc[d + 2], acc[d + 3]);
    }
}

// ---------------- Output GEMM (double-buffered): att[4096,1024] @ W_out[1024,1024] + b ----------------
__global__ __launch_bounds__(256) void out_gemm_kernel(
    const float* __restrict__ B, const float* __restrict__ bias,
    float* __restrict__ C) {
    const int K = DMODEL;
    const int N = DMODEL;
    __shared__ float As[2][16][132];
    __shared__ float Bs[2][16][132];

    int tid = threadIdx.x;
    int m0 = blockIdx.y * 128;
    int n0 = blockIdx.x * 128;
    int trow = tid / 16;
    int tcol = tid % 16;

    int arow[2], akc[2], brow[2], bnc[2];
#pragma unroll
    for (int t = 0; t < 2; t++) {
        int idx = tid + 256 * t;
        arow[t] = idx >> 2;  akc[t] = idx & 3;
        brow[t] = idx >> 5;  bnc[t] = idx & 31;
    }

    float acc[8][8];
#pragma unroll
    for (int i = 0; i < 8; i++)
#pragma unroll
        for (int j = 0; j < 8; j++) acc[i][j] = 0.f;

    const float* A = g_att;
    float4 pa[2], pb[2];
#pragma unroll
    for (int t = 0; t < 2; t++) {
        pa[t] = *(const float4*)&A[(size_t)(m0 + arow[t]) * K + 4 * akc[t]];
        pb[t] = *(const float4*)&B[(size_t)brow[t] * N + n0 + 4 * bnc[t]];
    }
#pragma unroll
    for (int t = 0; t < 2; t++) {
        As[0][4 * akc[t] + 0][arow[t]] = pa[t].x;
        As[0][4 * akc[t] + 1][arow[t]] = pa[t].y;
        As[0][4 * akc[t] + 2][arow[t]] = pa[t].z;
        As[0][4 * akc[t] + 3][arow[t]] = pa[t].w;
        *(float4*)&Bs[0][brow[t]][4 * bnc[t]] = pb[t];
    }
    __syncthreads();

    int buf = 0;
    for (int k0 = 0; k0 < K; k0 += 16) {
        int kn = k0 + 16;
        bool has_next = kn < K;
        if (has_next) {
#pragma unroll
            for (int t = 0; t < 2; t++) {
                pa[t] = *(const float4*)&A[(size_t)(m0 + arow[t]) * K + kn + 4 * akc[t]];
                pb[t] = *(const float4*)&B[(size_t)(kn + brow[t]) * N + n0 + 4 * bnc[t]];
            }
        }
#pragma unroll
        for (int kk = 0; kk < 16; kk++) {
            float a[8], b[8];
            *(float4*)&a[0] = *(const float4*)&As[buf][kk][trow * 8];
            *(float4*)&a[4] = *(const float4*)&As[buf][kk][trow * 8 + 4];
            *(float4*)&b[0] = *(const float4*)&Bs[buf][kk][tcol * 8];
            *(float4*)&b[4] = *(const float4*)&Bs[buf][kk][tcol * 8 + 4];
#pragma unroll
            for (int i = 0; i < 8; i++)
#pragma unroll
                for (int j = 0; j < 8; j++) acc[i][j] += a[i] * b[j];
        }
        if (has_next) {
            int nb = buf ^ 1;
#pragma unroll
            for (int t = 0; t < 2; t++) {
                As[nb][4 * akc[t] + 0][arow[t]] = pa[t].x;
                As[nb][4 * akc[t] + 1][arow[t]] = pa[t].y;
                As[nb][4 * akc[t] + 2][arow[t]] = pa[t].z;
                As[nb][4 * akc[t] + 3][arow[t]] = pa[t].w;
                *(float4*)&Bs[nb][brow[t]][4 * bnc[t]] = pb[t];
            }
            __syncthreads();
            buf = nb;
        }
    }

#pragma unroll
    for (int i = 0; i < 8; i++) {
        int mrow = m0 + trow * 8 + i;
#pragma unroll
        for (int j = 0; j < 8; j += 4) {
            int n = n0 + tcol * 8 + j;
            float4 v;
            v.x = acc[i][j + 0] + bias[n + 0];
            v.y = acc[i][j + 1] + bias[n + 1];
            v.z = acc[i][j + 2] + bias[n + 2];
            v.w = acc[i][j + 3] + bias[n + 3];
            *(float4*)&C[(size_t)mrow * N + n] = v;
        }
    }
}

// ---------------- launch ----------------
extern "C" void kernel_launch(void* const* d_in, const int* in_sizes, int n_in,
                              void* d_out, int out_size) {
    const float* x     = (const float*)d_in[0];
    const float* W_qkv = (const float*)d_in[1];
    const float* b_qkv = (const float*)d_in[2];
    const float* W_out = (const float*)d_in[3];
    const float* b_out = (const float*)d_in[4];
    float* out = (float*)d_out;

    rope_table_kernel<<<(SEQ * 32 + 255) / 256, 256>>>();
    qkv_gemm_kernel<<<dim3(3 * DMODEL / 128, BATCH * SEQ / 128), 256>>>(x, W_qkv, b_qkv);
    rope_apply_kernel<<<(BATCH * NHEADS * SEQ * 32 + 255) / 256, 256>>>();
    attn_kernel<<<dim3(SEQ / 64, BATCH * NHEADS), 256>>>();
    out_gemm_kernel<<<dim3(DMODEL / 128, BATCH * SEQ / 128), 256>>>(W_out, b_out, out);
}

// round 7
// speedup vs baseline: 1.5471x; 1.5471x over previous
#include <cuda_runtime.h>
#include <math.h>

#define BATCH   2
#define SEQ     2048
#define DMODEL  1024
#define NHEADS  16
#define HD      64

// ---------------- scratch (no allocations allowed) ----------------
__device__ float g_Q[BATCH * NHEADS * SEQ * HD];     // 16 MB
__device__ float g_K[BATCH * NHEADS * SEQ * HD];     // 16 MB
__device__ float g_V[BATCH * NHEADS * SEQ * HD];     // 16 MB
__device__ float g_att[BATCH * SEQ * DMODEL];        // 16 MB
__device__ float g_cos[SEQ * 32];
__device__ float g_sin[SEQ * 32];

// ---------------- RoPE table (fp64 for large-angle accuracy) ----------------
__global__ void rope_table_kernel() {
    int idx = blockIdx.x * blockDim.x + threadIdx.x;
    if (idx >= SEQ * 32) return;
    int s = idx / 32, i = idx % 32;
    double inv = exp(-((double)(2 * i) / 64.0) * log(10000.0));
    double ang = (double)s * inv;
    double sn, cs;
    sincos(ang, &sn, &cs);
    g_cos[idx] = (float)cs;
    g_sin[idx] = (float)sn;
}

// ---------------- QKV GEMM (double-buffered): x[4096,1024] @ W[1024,3072] + b ----------------
__global__ __launch_bounds__(256) void qkv_gemm_kernel(
    const float* __restrict__ A, const float* __restrict__ B,
    const float* __restrict__ bias) {
    const int K = DMODEL;          // 1024
    const int N = 3 * DMODEL;      // 3072
    __shared__ float As[2][16][132];
    __shared__ float Bs[2][16][132];

    int tid = threadIdx.x;
    int m0 = blockIdx.y * 128;
    int n0 = blockIdx.x * 128;
    int trow = tid / 16;           // 0..15
    int tcol = tid % 16;           // 0..15

    int arow[2], akc[2], brow[2], bnc[2];
#pragma unroll
    for (int t = 0; t < 2; t++) {
        int idx = tid + 256 * t;
        arow[t] = idx >> 2;  akc[t] = idx & 3;
        brow[t] = idx >> 5;  bnc[t] = idx & 31;
    }

    float acc[8][8];
#pragma unroll
    for (int i = 0; i < 8; i++)
#pragma unroll
        for (int j = 0; j < 8; j++) acc[i][j] = 0.f;

    float4 pa[2], pb[2];
#pragma unroll
    for (int t = 0; t < 2; t++) {
        pa[t] = *(const float4*)&A[(size_t)(m0 + arow[t]) * K + 4 * akc[t]];
        pb[t] = *(const float4*)&B[(size_t)brow[t] * N + n0 + 4 * bnc[t]];
    }
#pragma unroll
    for (int t = 0; t < 2; t++) {
        As[0][4 * akc[t] + 0][arow[t]] = pa[t].x;
        As[0][4 * akc[t] + 1][arow[t]] = pa[t].y;
        As[0][4 * akc[t] + 2][arow[t]] = pa[t].z;
        As[0][4 * akc[t] + 3][arow[t]] = pa[t].w;
        *(float4*)&Bs[0][brow[t]][4 * bnc[t]] = pb[t];
    }
    __syncthreads();

    int buf = 0;
    for (int k0 = 0; k0 < K; k0 += 16) {
        int kn = k0 + 16;
        bool has_next = kn < K;
        if (has_next) {
#pragma unroll
            for (int t = 0; t < 2; t++) {
                pa[t] = *(const float4*)&A[(size_t)(m0 + arow[t]) * K + kn + 4 * akc[t]];
                pb[t] = *(const float4*)&B[(size_t)(kn + brow[t]) * N + n0 + 4 * bnc[t]];
            }
        }
#pragma unroll
        for (int kk = 0; kk < 16; kk++) {
            float a[8], b[8];
            *(float4*)&a[0] = *(const float4*)&As[buf][kk][trow * 8];
            *(float4*)&a[4] = *(const float4*)&As[buf][kk][trow * 8 + 4];
            *(float4*)&b[0] = *(const float4*)&Bs[buf][kk][tcol * 8];
            *(float4*)&b[4] = *(const float4*)&Bs[buf][kk][tcol * 8 + 4];
#pragma unroll
            for (int i = 0; i < 8; i++)
#pragma unroll
                for (int j = 0; j < 8; j++) acc[i][j] += a[i] * b[j];
        }
        if (has_next) {
            int nb = buf ^ 1;
#pragma unroll
            for (int t = 0; t < 2; t++) {
                As[nb][4 * akc[t] + 0][arow[t]] = pa[t].x;
                As[nb][4 * akc[t] + 1][arow[t]] = pa[t].y;
                As[nb][4 * akc[t] + 2][arow[t]] = pa[t].z;
                As[nb][4 * akc[t] + 3][arow[t]] = pa[t].w;
                *(float4*)&Bs[nb][brow[t]][4 * bnc[t]] = pb[t];
            }
            __syncthreads();
            buf = nb;
        }
    }

    // epilogue: bias + scatter into [B,H,S,hd] layout
#pragma unroll
    for (int i = 0; i < 8; i++) {
        int m = m0 + trow * 8 + i;
        int bb = m / SEQ, s = m % SEQ;
#pragma unroll
        for (int j = 0; j < 8; j += 4) {
            int n = n0 + tcol * 8 + j;
            float4 v;
            v.x = acc[i][j + 0] + bias[n + 0];
            v.y = acc[i][j + 1] + bias[n + 1];
            v.z = acc[i][j + 2] + bias[n + 2];
            v.w = acc[i][j + 3] + bias[n + 3];
            int which = n / DMODEL;            // 0=Q 1=K 2=V
            int nn = n % DMODEL;
            int h = nn / HD, d = nn % HD;      // 4-aligned, same head within float4
            float* dst = (which == 0) ? g_Q : (which == 1) ? g_K : g_V;
            *(float4*)&dst[(size_t)((bb * NHEADS + h) * SEQ + s) * HD + d] = v;
        }
    }
}

// ---------------- RoPE apply (in-place on Q and K) ----------------
__global__ void rope_apply_kernel() {
    int idx = blockIdx.x * blockDim.x + threadIdx.x;
    const int total = BATCH * NHEADS * SEQ * 32;
    if (idx >= total) return;
    int d = idx & 31;
    int s = (idx >> 5) & (SEQ - 1);
    int bh = idx / (32 * SEQ);
    float c = g_cos[s * 32 + d];
    float sn = g_sin[s * 32 + d];
    size_t base = (size_t)(bh * SEQ + s) * HD;
    float q0 = g_Q[base + d], q1 = g_Q[base + d + 32];
    g_Q[base + d]      = q0 * c - q1 * sn;
    g_Q[base + d + 32] = q1 * c + q0 * sn;
    float k0 = g_K[base + d], k1 = g_K[base + d + 32];
    g_K[base + d]      = k0 * c - k1 * sn;
    g_K[base + d + 32] = k1 * c + k0 * sn;
}

// ---------------- Flash attention v2b: swizzled row-major micro-GEMM ----------------
// 256 threads, thread (ty=tid/16, tx=tid%16):
//   score: S[ty4+i][tx4+k] = sum_d Q[row][d]*K[key][d], d-chunked by 4
//   PV:    O[ty4+i][tx4+k] += sum_j P[row][j]*V[j][col], j-chunked by 4
// All tiles [64][64] row-major in smem with chunk swizzle
//   phys = row*64 + ((col>>2 ^ (row>>2 & 7))<<2)  -> every float4 aligned;
// quarter-warp phases see 8 distinct bank quads on K/V reads (conflict-free)
// and ty-broadcast on Q/P reads.
#define SW(row, c4) ((row) * 64 + ((((c4) >> 2) ^ (((row) >> 2) & 7)) << 2))
#define AT_SMEM_BYTES (4 * 64 * 64 * 4)

__global__ __launch_bounds__(256, 2) void attn_kernel() {
    extern __shared__ float sm[];
    float* Qs = sm;              // [64 q][64 d]
    float* Ks = sm + 4096;       // [64 key][64 d]
    float* Ps = sm + 8192;       // [64 q][64 key]
    float* Vs = sm + 12288;      // [64 key][64 d]

    int tid = threadIdx.x;
    int qt = blockIdx.x;           // q tile 0..31
    int bh = blockIdx.y;           // 0..31
    int ty = tid >> 4;             // 0..15 -> q rows ty*4..+3
    int tx = tid & 15;             // 0..15 -> keys / d-cols tx*4..+3
    const float scale = 0.125f;    // 1/sqrt(64)

    const float* Qg = &g_Q[(size_t)(bh * SEQ + qt * 64) * HD];
    const float* Kg = &g_K[(size_t)bh * SEQ * HD];
    const float* Vg = &g_V[(size_t)bh * SEQ * HD];

    // load Q tile row-major (swizzled)
#pragma unroll
    for (int t = 0; t < 4; t++) {
        int lin = tid + 256 * t;             // 0..1023
        int j = lin >> 4, dc = lin & 15;
        *(float4*)&Qs[SW(j, dc * 4)] = *(const float4*)&Qg[j * HD + dc * 4];
    }

    float o[4][4];
    float m[4], l[4];
#pragma unroll
    for (int i = 0; i < 4; i++) {
        m[i] = -1e30f; l[i] = 0.f;
#pragma unroll
        for (int k = 0; k < 4; k++) o[i][k] = 0.f;
    }

    for (int kt = 0; kt <= qt; kt++) {
        __syncthreads();   // prior PV reads of Ps/Vs done; Q stores done (kt==0)
#pragma unroll
        for (int t = 0; t < 4; t++) {
            int lin = tid + 256 * t;
            int j = lin >> 4, dc = lin & 15;
            *(float4*)&Ks[SW(j, dc * 4)] =
                *(const float4*)&Kg[(size_t)(kt * 64 + j) * HD + dc * 4];
            *(float4*)&Vs[SW(j, dc * 4)] =
                *(const float4*)&Vg[(size_t)(kt * 64 + j) * HD + dc * 4];
        }
        __syncthreads();

        // ---- score micro-GEMM (d-chunks of 4)
        float s[4][4];
#pragma unroll
        for (int i = 0; i < 4; i++)
#pragma unroll
            for (int k = 0; k < 4; k++) s[i][k] = 0.f;
#pragma unroll 4
        for (int d0 = 0; d0 < 64; d0 += 4) {
            float qv[4][4], kv[4][4];
#pragma unroll
            for (int i = 0; i < 4; i++)
                *(float4*)qv[i] = *(const float4*)&Qs[SW(ty * 4 + i, d0)];
#pragma unroll
            for (int k = 0; k < 4; k++)
                *(float4*)kv[k] = *(const float4*)&Ks[SW(tx * 4 + k, d0)];
#pragma unroll
            for (int i = 0; i < 4; i++)
#pragma unroll
                for (int k = 0; k < 4; k++) {
                    s[i][k] += qv[i][0] * kv[k][0];
                    s[i][k] += qv[i][1] * kv[k][1];
                    s[i][k] += qv[i][2] * kv[k][2];
                    s[i][k] += qv[i][3] * kv[k][3];
                }
        }

        // scale + causal mask
        int qbase = qt * 64 + ty * 4;
        int kbase = kt * 64 + tx * 4;
#pragma unroll
        for (int i = 0; i < 4; i++)
#pragma unroll
            for (int k = 0; k < 4; k++) {
                float v = s[i][k] * scale;
                s[i][k] = (kbase + k > qbase + i) ? -1e30f : v;
            }

        // ---- online softmax (per q row, across the 16-lane tx group)
#pragma unroll
        for (int i = 0; i < 4; i++) {
            float mloc = fmaxf(fmaxf(s[i][0], s[i][1]), fmaxf(s[i][2], s[i][3]));
            mloc = fmaxf(mloc, __shfl_xor_sync(0xffffffffu, mloc, 1));
            mloc = fmaxf(mloc, __shfl_xor_sync(0xffffffffu, mloc, 2));
            mloc = fmaxf(mloc, __shfl_xor_sync(0xffffffffu, mloc, 4));
            mloc = fmaxf(mloc, __shfl_xor_sync(0xffffffffu, mloc, 8));
            float mnew = fmaxf(m[i], mloc);
            float corr = __expf(m[i] - mnew);
            l[i] *= corr;
#pragma unroll
            for (int k = 0; k < 4; k++) o[i][k] *= corr;
            float rs = 0.f;
#pragma unroll
            for (int k = 0; k < 4; k++) {
                float e = __expf(s[i][k] - mnew);
                s[i][k] = e;
                rs += e;
            }
            rs += __shfl_xor_sync(0xffffffffu, rs, 1);
            rs += __shfl_xor_sync(0xffffffffu, rs, 2);
            rs += __shfl_xor_sync(0xffffffffu, rs, 4);
            rs += __shfl_xor_sync(0xffffffffu, rs, 8);
            l[i] += rs;
            m[i] = mnew;
        }

        // ---- write P row-major: Ps[q][key]
#pragma unroll
        for (int i = 0; i < 4; i++) {
            float4 w = make_float4(s[i][0], s[i][1], s[i][2], s[i][3]);
            *(float4*)&Ps[SW(ty * 4 + i, tx * 4)] = w;
        }
        __syncthreads();

        // ---- PV micro-GEMM (j-chunks of 4)
#pragma unroll 4
        for (int j0 = 0; j0 < 64; j0 += 4) {
            float pv[4][4], vv[4][4];
#pragma unroll
            for (int i = 0; i < 4; i++)
                *(float4*)pv[i] = *(const float4*)&Ps[SW(ty * 4 + i, j0)];
#pragma unroll
            for (int jj = 0; jj < 4; jj++)
                *(float4*)vv[jj] = *(const float4*)&Vs[SW(j0 + jj, tx * 4)];
#pragma unroll
            for (int i = 0; i < 4; i++)
#pragma unroll
                for (int k = 0; k < 4; k++) {
                    o[i][k] += pv[i][0] * vv[0][k];
                    o[i][k] += pv[i][1] * vv[1][k];
                    o[i][k] += pv[i][2] * vv[2][k];
                    o[i][k] += pv[i][3] * vv[3][k];
                }
        }
    }

    // ---- epilogue: normalize and write [B,S,D] with head offset
    int bb = bh >> 4, h = bh & 15;
#pragma unroll
    for (int i = 0; i < 4; i++) {
        float inv = 1.f / l[i];
        int srow = qt * 64 + ty * 4 + i;
        float4 w = make_float4(o[i][0] * inv, o[i][1] * inv,
                               o[i][2] * inv, o[i][3] * inv);
        *(float4*)&g_att[(size_t)(bb * SEQ + srow) * DMODEL + h * HD + tx * 4] = w;
    }
}

// ---------------- Output GEMM (double-buffered): att[4096,1024] @ W_out[1024,1024] + b ----------------
__global__ __launch_bounds__(256) void out_gemm_kernel(
    const float* __restrict__ B, const float* __restrict__ bias,
    float* __restrict__ C) {
    const int K = DMODEL;
    const int N = DMODEL;
    __shared__ float As[2][16][132];
    __shared__ float Bs[2][16][132];

    int tid = threadIdx.x;
    int m0 = blockIdx.y * 128;
    int n0 = blockIdx.x * 128;
    int trow = tid / 16;
    int tcol = tid % 16;

    int arow[2], akc[2], brow[2], bnc[2];
#pragma unroll
    for (int t = 0; t < 2; t++) {
        int idx = tid + 256 * t;
        arow[t] = idx >> 2;  akc[t] = idx & 3;
        brow[t] = idx >> 5;  bnc[t] = idx & 31;
    }

    float acc[8][8];
#pragma unroll
    for (int i = 0; i < 8; i++)
#pragma unroll
        for (int j = 0; j < 8; j++) acc[i][j] = 0.f;

    const float* A = g_att;
    float4 pa[2], pb[2];
#pragma unroll
    for (int t = 0; t < 2; t++) {
        pa[t] = *(const float4*)&A[(size_t)(m0 + arow[t]) * K + 4 * akc[t]];
        pb[t] = *(const float4*)&B[(size_t)brow[t] * N + n0 + 4 * bnc[t]];
    }
#pragma unroll
    for (int t = 0; t < 2; t++) {
        As[0][4 * akc[t] + 0][arow[t]] = pa[t].x;
        As[0][4 * akc[t] + 1][arow[t]] = pa[t].y;
        As[0][4 * akc[t] + 2][arow[t]] = pa[t].z;
        As[0][4 * akc[t] + 3][arow[t]] = pa[t].w;
        *(float4*)&Bs[0][brow[t]][4 * bnc[t]] = pb[t];
    }
    __syncthreads();

    int buf = 0;
    for (int k0 = 0; k0 < K; k0 += 16) {
        int kn = k0 + 16;
        bool has_next = kn < K;
        if (has_next) {
#pragma unroll
            for (int t = 0; t < 2; t++) {
                pa[t] = *(const float4*)&A[(size_t)(m0 + arow[t]) * K + kn + 4 * akc[t]];
                pb[t] = *(const float4*)&B[(size_t)(kn + brow[t]) * N + n0 + 4 * bnc[t]];
            }
        }
#pragma unroll
        for (int kk = 0; kk < 16; kk++) {
            float a[8], b[8];
            *(float4*)&a[0] = *(const float4*)&As[buf][kk][trow * 8];
            *(float4*)&a[4] = *(const float4*)&As[buf][kk][trow * 8 + 4];
            *(float4*)&b[0] = *(const float4*)&Bs[buf][kk][tcol * 8];
            *(float4*)&b[4] = *(const float4*)&Bs[buf][kk][tcol * 8 + 4];
#pragma unroll
            for (int i = 0; i < 8; i++)
#pragma unroll
                for (int j = 0; j < 8; j++) acc[i][j] += a[i] * b[j];
        }
        if (has_next) {
            int nb = buf ^ 1;
#pragma unroll
            for (int t = 0; t < 2; t++) {
                As[nb][4 * akc[t] + 0][arow[t]] = pa[t].x;
                As[nb][4 * akc[t] + 1][arow[t]] = pa[t].y;
                As[nb][4 * akc[t] + 2][arow[t]] = pa[t].z;
                As[nb][4 * akc[t] + 3][arow[t]] = pa[t].w;
                *(float4*)&Bs[nb][brow[t]][4 * bnc[t]] = pb[t];
            }
            __syncthreads();
            buf = nb;
        }
    }

#pragma unroll
    for (int i = 0; i < 8; i++) {
        int mrow = m0 + trow * 8 + i;
#pragma unroll
        for (int j = 0; j < 8; j += 4) {
            int n = n0 + tcol * 8 + j;
            float4 v;
            v.x = acc[i][j + 0] + bias[n + 0];
            v.y = acc[i][j + 1] + bias[n + 1];
            v.z = acc[i][j + 2] + bias[n + 2];
            v.w = acc[i][j + 3] + bias[n + 3];
            *(float4*)&C[(size_t)mrow * N + n] = v;
        }
    }
}

// ---------------- launch ----------------
extern "C" void kernel_launch(void* const* d_in, const int* in_sizes, int n_in,
                              void* d_out, int out_size) {
    const float* x     = (const float*)d_in[0];
    const float* W_qkv = (const float*)d_in[1];
    const float* b_qkv = (const float*)d_in[2];
    const float* W_out = (const float*)d_in[3];
    const float* b_out = (const float*)d_in[4];
    float* out = (float*)d_out;

    cudaFuncSetAttribute(attn_kernel,
                         cudaFuncAttributeMaxDynamicSharedMemorySize,
                         AT_SMEM_BYTES);

    rope_table_kernel<<<(SEQ * 32 + 255) / 256, 256>>>();
    qkv_gemm_kernel<<<dim3(3 * DMODEL / 128, BATCH * SEQ / 128), 256>>>(x, W_qkv, b_qkv);
    rope_apply_kernel<<<(BATCH * NHEADS * SEQ * 32 + 255) / 256, 256>>>();
    attn_kernel<<<dim3(SEQ / 64, BATCH * NHEADS), 256, AT_SMEM_BYTES>>>();
    out_gemm_kernel<<<dim3(DMODEL / 128, BATCH * SEQ / 128), 256>>>(W_out, b_out, out);
}